// round 8
// baseline (speedup 1.0000x reference)
#include <cuda_runtime.h>
#include <math.h>

#define NQ       10
#define DIM      1024
#define NL       3
#define NG       (NL * NQ)
#define PI_F     3.14159265358979f

// ---------------- packed f32x2 helpers (sm_103a) ----------------
union F2U { float2 f; unsigned long long u; };

__device__ __forceinline__ float2 f2mul(float2 a, float2 b) {
    F2U A, B, D; A.f = a; B.f = b;
    asm("mul.rn.f32x2 %0, %1, %2;" : "=l"(D.u) : "l"(A.u), "l"(B.u));
    return D.f;
}
__device__ __forceinline__ float2 f2fma(float2 a, float2 b, float2 c) {
    F2U A, B, C, D; A.f = a; B.f = b; C.f = c;
    asm("fma.rn.f32x2 %0, %1, %2, %3;" : "=l"(D.u) : "l"(A.u), "l"(B.u), "l"(C.u));
    return D.f;
}
__device__ __forceinline__ float2 cmul(float2 a, float2 b) {
    return make_float2(a.x * b.x - a.y * b.y, a.x * b.y + a.y * b.x);
}

// Composed 10-CNOT ring: state_new[k] = state_old[P(k)]
__device__ __forceinline__ int cnot_perm(int k) {
    return k ^ (k >> 1) ^ ((-(k & 1)) & 0x300);
}

// XOR bank swizzle: injects bits 8..5 into bits 3..0 (conflict-free for all
// six access patterns used below; verified bit-by-bit).
__device__ __forceinline__ int physk(int k) { return k ^ ((k >> 5) & 15); }

// Canonical index of thread-local amp r for each layout (L=lane, w=warp bit).
// Layout1: k = [L4..L0 | w | r3..r0]          (reg bits = qubits 6..9)
__device__ __forceinline__ int k1i(int L, int w, int r) {
    return (L << 5) | (w << 4) | r;
}
// Layout2: k = [L4 L3 | r3..r0 | w | L2 L1 L0] (reg bits = qubits 2..5)
__device__ __forceinline__ int k2i(int L, int w, int r) {
    return ((L & 24) << 5) | (r << 4) | (w << 3) | (L & 7);
}
// Layout3: k = [r3 r2 | L4 L3 L2 | w | L1 L0 | r1 r0] (reg bits incl. qubits 0,1)
__device__ __forceinline__ int k3i(int L, int w, int r) {
    return ((r & 12) << 6) | ((L & 28) << 3) | (w << 4) | ((L & 3) << 2) | (r & 3);
}

// Gate coefficients packed per u-element as (x, x, -y, y); order u00,u01,u10,u11.
__device__ float4 g_gco[NG][4];

// ---------------- prep: fuse RZ*RY*RX per (layer,qubit) ----------------
__global__ void vq_prep(const float* __restrict__ w) {
    const int t = threadIdx.x;
    if (t >= NG) return;
    const float ax = w[t * 3 + 0], ay = w[t * 3 + 1], az = w[t * 3 + 2];
    float ca, sa, cb, sb, cg, sg;
    sincosf(0.5f * ax, &sa, &ca);
    sincosf(0.5f * ay, &sb, &cb);
    sincosf(0.5f * az, &sg, &cg);
    const float2 M00 = make_float2( cb * ca,  sb * sa);
    const float2 M01 = make_float2(-sb * ca, -cb * sa);
    const float2 M10 = make_float2( sb * ca, -cb * sa);
    const float2 M11 = make_float2( cb * ca, -sb * sa);
    const float2 e0 = make_float2(cg, -sg);
    const float2 e1 = make_float2(cg,  sg);
    const float2 u00 = cmul(e0, M00), u01 = cmul(e0, M01);
    const float2 u10 = cmul(e1, M10), u11 = cmul(e1, M11);
    g_gco[t][0] = make_float4(u00.x, u00.x, -u00.y, u00.y);
    g_gco[t][1] = make_float4(u01.x, u01.x, -u01.y, u01.y);
    g_gco[t][2] = make_float4(u10.x, u10.x, -u10.y, u10.y);
    g_gco[t][3] = make_float4(u11.x, u11.x, -u11.y, u11.y);
}

// Apply fused gate with register-bit mask RM to 16 register-resident amps.
template<int RM>
__device__ __forceinline__ void apply_gate16(float2 a[16], int g) {
    const float4 q0 = __ldg(&g_gco[g][0]);
    const float4 q1 = __ldg(&g_gco[g][1]);
    const float4 q2 = __ldg(&g_gco[g][2]);
    const float4 q3 = __ldg(&g_gco[g][3]);
    const float2 u00x = make_float2(q0.x, q0.y), u00m = make_float2(q0.z, q0.w);
    const float2 u01x = make_float2(q1.x, q1.y), u01m = make_float2(q1.z, q1.w);
    const float2 u10x = make_float2(q2.x, q2.y), u10m = make_float2(q2.z, q2.w);
    const float2 u11x = make_float2(q3.x, q3.y), u11m = make_float2(q3.z, q3.w);
#pragma unroll
    for (int r = 0; r < 16; ++r) {
        if (r & RM) continue;
        const float2 a0 = a[r];
        const float2 a1 = a[r | RM];
        const float2 s0 = make_float2(a0.y, a0.x);
        const float2 s1 = make_float2(a1.y, a1.x);
        float2 r0 = f2mul(u00x, a0);
        r0 = f2fma(u00m, s0, r0);
        r0 = f2fma(u01x, a1, r0);
        r0 = f2fma(u01m, s1, r0);
        float2 r1 = f2mul(u10x, a0);
        r1 = f2fma(u10m, s0, r1);
        r1 = f2fma(u11x, a1, r1);
        r1 = f2fma(u11m, s1, r1);
        a[r]      = r0;
        a[r | RM] = r1;
    }
}

// ---------------- main: 2 warps = 1 batch element (16 amps/thread) ----------------
__global__ __launch_bounds__(128, 6)
void vq_main(const float* __restrict__ x, float* __restrict__ out) {
    __shared__ float2 st[2][DIM];           // one 8KB buffer per warp-pair
    __shared__ float  redsc[2][2][NQ];

    const int t   = threadIdx.x;
    const int pid = t >> 6;                 // warp-pair within block (0,1)
    const int w   = (t >> 5) & 1;           // warp bit within pair
    const int L   = t & 31;
    const int b   = blockIdx.x * 2 + pid;
    float2* const S = st[pid];
    const int barid = pid + 1;

#define BARP() asm volatile("bar.sync %0, 64;" :: "r"(barid) : "memory")

    // ---- encoding angles (per warp, lanes 0..9 compute, shfl broadcast) ----
    float c = 1.0f, s = 0.0f;
    if (L < NQ) {
        const float a = tanhf(x[b * NQ + L]) * PI_F;
        sincosf(0.5f * a, &s, &c);
    }
    float cq[NQ], sq[NQ];
#pragma unroll
    for (int q = 0; q < NQ; ++q) {
        cq[q] = __shfl_sync(0xffffffffu, c, q);
        sq[q] = __shfl_sync(0xffffffffu, s, q);
    }

    // ---- initial state = enc evaluated at P(k1)  (layer-0 perm folded in) ----
    float2 a[16];
#pragma unroll
    for (int r = 0; r < 16; ++r) {
        const int j = cnot_perm(k1i(L, w, r));
        float f = 1.0f;
#pragma unroll
        for (int q = 0; q < NQ; ++q)
            f *= ((j >> (9 - q)) & 1) ? sq[q] : cq[q];
        a[r] = make_float2(f, 0.0f);
    }

    // ---- layers ----
#pragma unroll
    for (int l = 0; l < NL; ++l) {
        if (l > 0) {
            // CNOT-ring permutation: layout3 -> gather P -> layout1
            BARP();
#pragma unroll
            for (int r = 0; r < 16; ++r) S[physk(k3i(L, w, r))] = a[r];
            BARP();
#pragma unroll
            for (int r = 0; r < 16; ++r) a[r] = S[physk(cnot_perm(k1i(L, w, r)))];
        }

        // phase 1 (layout1): qubits 6..9 on reg bits 3..0
        apply_gate16<8>(a, l * NQ + 6);
        apply_gate16<4>(a, l * NQ + 7);
        apply_gate16<2>(a, l * NQ + 8);
        apply_gate16<1>(a, l * NQ + 9);

        // relayout 1 -> 2
        BARP();
#pragma unroll
        for (int r = 0; r < 16; ++r) S[physk(k1i(L, w, r))] = a[r];
        BARP();
#pragma unroll
        for (int r = 0; r < 16; ++r) a[r] = S[physk(k2i(L, w, r))];

        // phase 2 (layout2): qubits 2..5 on reg bits 3..0
        apply_gate16<8>(a, l * NQ + 2);
        apply_gate16<4>(a, l * NQ + 3);
        apply_gate16<2>(a, l * NQ + 4);
        apply_gate16<1>(a, l * NQ + 5);

        // relayout 2 -> 3
        BARP();
#pragma unroll
        for (int r = 0; r < 16; ++r) S[physk(k2i(L, w, r))] = a[r];
        BARP();
#pragma unroll
        for (int r = 0; r < 16; ++r) a[r] = S[physk(k3i(L, w, r))];

        // phase 3 (layout3): qubits 0,1 on reg bits 3,2
        apply_gate16<8>(a, l * NQ + 0);
        apply_gate16<4>(a, l * NQ + 1);
    }

    // ---- Z expectations (layout3 bit map):
    // q0:r3  q1:r2  q2:L4  q3:L3  q4:L2  q5:w  q6:L1  q7:L0  q8:r1  q9:r0
    float T = 0.0f, A0 = 0.0f, A1 = 0.0f, A8 = 0.0f, A9 = 0.0f;
#pragma unroll
    for (int r = 0; r < 16; ++r) {
        const float p = a[r].x * a[r].x + a[r].y * a[r].y;
        T  += p;
        A0 += (r & 8) ? -p : p;
        A1 += (r & 4) ? -p : p;
        A8 += (r & 2) ? -p : p;
        A9 += (r & 1) ? -p : p;
    }
    float red[NQ];
    red[0] = A0;
    red[1] = A1;
    red[2] = (L & 16) ? -T : T;
    red[3] = (L & 8)  ? -T : T;
    red[4] = (L & 4)  ? -T : T;
    red[5] = w        ? -T : T;
    red[6] = (L & 2)  ? -T : T;
    red[7] = (L & 1)  ? -T : T;
    red[8] = A8;
    red[9] = A9;

#pragma unroll
    for (int q = 0; q < NQ; ++q) {
#pragma unroll
        for (int off = 16; off > 0; off >>= 1)
            red[q] += __shfl_xor_sync(0xffffffffu, red[q], off);
    }
    if (L == 0) {
#pragma unroll
        for (int q = 0; q < NQ; ++q) redsc[pid][w][q] = red[q];
    }
    BARP();
    if (w == 0 && L < NQ)
        out[b * NQ + L] = redsc[pid][0][L] + redsc[pid][1][L];
#undef BARP
}

extern "C" void kernel_launch(void* const* d_in, const int* in_sizes, int n_in,
                              void* d_out, int out_size) {
    const float* x = (const float*)d_in[0];
    const float* w = (const float*)d_in[1];
    if (n_in >= 2 && in_sizes[0] == NG * 3 && in_sizes[1] != NG * 3) {
        x = (const float*)d_in[1];
        w = (const float*)d_in[0];
    }
    const int batch = out_size / NQ;            // 16384
    vq_prep<<<1, 32>>>(w);
    vq_main<<<batch / 2, 128>>>(x, (float*)d_out);
}

// round 9
// speedup vs baseline: 1.1138x; 1.1138x over previous
#include <cuda_runtime.h>
#include <math.h>

#define NQ       10
#define DIM      1024
#define NL       3
#define NG       (NL * NQ)
#define PI_F     3.14159265358979f

// ---------------- packed f32x2 helpers (sm_103a) ----------------
union F2U { float2 f; unsigned long long u; };

__device__ __forceinline__ float2 f2mul(float2 a, float2 b) {
    F2U A, B, D; A.f = a; B.f = b;
    asm("mul.rn.f32x2 %0, %1, %2;" : "=l"(D.u) : "l"(A.u), "l"(B.u));
    return D.f;
}
__device__ __forceinline__ float2 f2fma(float2 a, float2 b, float2 c) {
    F2U A, B, C, D; A.f = a; B.f = b; C.f = c;
    asm("fma.rn.f32x2 %0, %1, %2, %3;" : "=l"(D.u) : "l"(A.u), "l"(B.u), "l"(C.u));
    return D.f;
}
__device__ __forceinline__ float2 cmul(float2 a, float2 b) {
    return make_float2(a.x * b.x - a.y * b.y, a.x * b.y + a.y * b.x);
}

// Composed 10-CNOT ring: state_new[k] = state_old[P(k)]
__device__ __forceinline__ int cnot_perm(int k) {
    return k ^ (k >> 1) ^ ((-(k & 1)) & 0x300);
}

// XOR bank swizzle: injects bits 8..5 into bits 3..0 (conflict-free for all
// access patterns below; verified bit-by-bit).
__device__ __forceinline__ int physk(int k) { return k ^ ((k >> 5) & 15); }

// Canonical index of thread-local amp r for each layout (L=lane, w=warp bit).
// Layout1: k = [L4..L0 | w | r3..r0]          (reg bits = qubits 6..9)
__device__ __forceinline__ int k1i(int L, int w, int r) {
    return (L << 5) | (w << 4) | r;
}
// Layout2: k = [L4 L3 | r3..r0 | w | L2 L1 L0] (reg bits = qubits 2..5)
__device__ __forceinline__ int k2i(int L, int w, int r) {
    return ((L & 24) << 5) | (r << 4) | (w << 3) | (L & 7);
}
// Layout3: k = [r3 r2 | L4 L3 L2 | w | L1 L0 | r1 r0] (reg bits incl. qubits 0,1)
__device__ __forceinline__ int k3i(int L, int w, int r) {
    return ((r & 12) << 6) | ((L & 28) << 3) | (w << 4) | ((L & 3) << 2) | (r & 3);
}

// Gate coefficients packed per u-element as (x, x, -y, y); order u00,u01,u10,u11.
__device__ float4 g_gco[NG][4];

// ---------------- prep: fuse RZ*RY*RX per (layer,qubit) ----------------
__global__ void vq_prep(const float* __restrict__ w) {
    const int t = threadIdx.x;
    if (t >= NG) return;
    const float ax = w[t * 3 + 0], ay = w[t * 3 + 1], az = w[t * 3 + 2];
    float ca, sa, cb, sb, cg, sg;
    sincosf(0.5f * ax, &sa, &ca);
    sincosf(0.5f * ay, &sb, &cb);
    sincosf(0.5f * az, &sg, &cg);
    const float2 M00 = make_float2( cb * ca,  sb * sa);
    const float2 M01 = make_float2(-sb * ca, -cb * sa);
    const float2 M10 = make_float2( sb * ca, -cb * sa);
    const float2 M11 = make_float2( cb * ca, -sb * sa);
    const float2 e0 = make_float2(cg, -sg);
    const float2 e1 = make_float2(cg,  sg);
    const float2 u00 = cmul(e0, M00), u01 = cmul(e0, M01);
    const float2 u10 = cmul(e1, M10), u11 = cmul(e1, M11);
    g_gco[t][0] = make_float4(u00.x, u00.x, -u00.y, u00.y);
    g_gco[t][1] = make_float4(u01.x, u01.x, -u01.y, u01.y);
    g_gco[t][2] = make_float4(u10.x, u10.x, -u10.y, u10.y);
    g_gco[t][3] = make_float4(u11.x, u11.x, -u11.y, u11.y);
}

// Apply fused gate with register-bit mask RM to 16 register-resident amps.
template<int RM>
__device__ __forceinline__ void apply_gate16(float2 a[16], int g) {
    const float4 q0 = __ldg(&g_gco[g][0]);
    const float4 q1 = __ldg(&g_gco[g][1]);
    const float4 q2 = __ldg(&g_gco[g][2]);
    const float4 q3 = __ldg(&g_gco[g][3]);
    const float2 u00x = make_float2(q0.x, q0.y), u00m = make_float2(q0.z, q0.w);
    const float2 u01x = make_float2(q1.x, q1.y), u01m = make_float2(q1.z, q1.w);
    const float2 u10x = make_float2(q2.x, q2.y), u10m = make_float2(q2.z, q2.w);
    const float2 u11x = make_float2(q3.x, q3.y), u11m = make_float2(q3.z, q3.w);
#pragma unroll
    for (int r = 0; r < 16; ++r) {
        if (r & RM) continue;
        const float2 a0 = a[r];
        const float2 a1 = a[r | RM];
        const float2 s0 = make_float2(a0.y, a0.x);
        const float2 s1 = make_float2(a1.y, a1.x);
        float2 r0 = f2mul(u00x, a0);
        r0 = f2fma(u00m, s0, r0);
        r0 = f2fma(u01x, a1, r0);
        r0 = f2fma(u01m, s1, r0);
        float2 r1 = f2mul(u10x, a0);
        r1 = f2fma(u10m, s0, r1);
        r1 = f2fma(u11x, a1, r1);
        r1 = f2fma(u11m, s1, r1);
        a[r]      = r0;
        a[r | RM] = r1;
    }
}

// ---------------- main: 1 block (2 warps, 64 thr) = 1 batch element ----------------
__global__ __launch_bounds__(64, 12)
void vq_main(const float* __restrict__ x, float* __restrict__ out) {
    __shared__ float2 S[DIM];              // 8 KB statevector buffer
    __shared__ float  redsc[2][NQ];

    const int t = threadIdx.x;
    const int w = t >> 5;                  // warp bit (qubit position per layouts)
    const int L = t & 31;
    const int b = blockIdx.x;

    // ---- encoding angles (lanes 0..9 compute, shfl broadcast within warp) ----
    float c = 1.0f, s = 0.0f;
    if (L < NQ) {
        const float a = tanhf(x[b * NQ + L]) * PI_F;
        sincosf(0.5f * a, &s, &c);
    }
    float cq[NQ], sq[NQ];
#pragma unroll
    for (int q = 0; q < NQ; ++q) {
        cq[q] = __shfl_sync(0xffffffffu, c, q);
        sq[q] = __shfl_sync(0xffffffffu, s, q);
    }

    // ---- initial state = enc evaluated at P(k1)  (layer-0 perm folded in) ----
    float2 a[16];
#pragma unroll
    for (int r = 0; r < 16; ++r) {
        const int j = cnot_perm(k1i(L, w, r));
        float f = 1.0f;
#pragma unroll
        for (int q = 0; q < NQ; ++q)
            f *= ((j >> (9 - q)) & 1) ? sq[q] : cq[q];
        a[r] = make_float2(f, 0.0f);
    }

    // ---- layers ----
#pragma unroll
    for (int l = 0; l < NL; ++l) {
        if (l > 0) {
            // CNOT-ring permutation: layout3 -> gather P -> layout1
            __syncthreads();
#pragma unroll
            for (int r = 0; r < 16; ++r) S[physk(k3i(L, w, r))] = a[r];
            __syncthreads();
#pragma unroll
            for (int r = 0; r < 16; ++r) a[r] = S[physk(cnot_perm(k1i(L, w, r)))];
        }

        // phase 1 (layout1): qubits 6..9 on reg bits 3..0
        apply_gate16<8>(a, l * NQ + 6);
        apply_gate16<4>(a, l * NQ + 7);
        apply_gate16<2>(a, l * NQ + 8);
        apply_gate16<1>(a, l * NQ + 9);

        // relayout 1 -> 2
        __syncthreads();
#pragma unroll
        for (int r = 0; r < 16; ++r) S[physk(k1i(L, w, r))] = a[r];
        __syncthreads();
#pragma unroll
        for (int r = 0; r < 16; ++r) a[r] = S[physk(k2i(L, w, r))];

        // phase 2 (layout2): qubits 2..5 on reg bits 3..0
        apply_gate16<8>(a, l * NQ + 2);
        apply_gate16<4>(a, l * NQ + 3);
        apply_gate16<2>(a, l * NQ + 4);
        apply_gate16<1>(a, l * NQ + 5);

        // relayout 2 -> 3
        __syncthreads();
#pragma unroll
        for (int r = 0; r < 16; ++r) S[physk(k2i(L, w, r))] = a[r];
        __syncthreads();
#pragma unroll
        for (int r = 0; r < 16; ++r) a[r] = S[physk(k3i(L, w, r))];

        // phase 3 (layout3): qubits 0,1 on reg bits 3,2
        apply_gate16<8>(a, l * NQ + 0);
        apply_gate16<4>(a, l * NQ + 1);
    }

    // ---- Z expectations (layout3 bit map):
    // q0:r3  q1:r2  q2:L4  q3:L3  q4:L2  q5:w  q6:L1  q7:L0  q8:r1  q9:r0
    float T = 0.0f, A0 = 0.0f, A1 = 0.0f, A8 = 0.0f, A9 = 0.0f;
#pragma unroll
    for (int r = 0; r < 16; ++r) {
        const float p = a[r].x * a[r].x + a[r].y * a[r].y;
        T  += p;
        A0 += (r & 8) ? -p : p;
        A1 += (r & 4) ? -p : p;
        A8 += (r & 2) ? -p : p;
        A9 += (r & 1) ? -p : p;
    }
    float red[NQ];
    red[0] = A0;
    red[1] = A1;
    red[2] = (L & 16) ? -T : T;
    red[3] = (L & 8)  ? -T : T;
    red[4] = (L & 4)  ? -T : T;
    red[5] = w        ? -T : T;
    red[6] = (L & 2)  ? -T : T;
    red[7] = (L & 1)  ? -T : T;
    red[8] = A8;
    red[9] = A9;

#pragma unroll
    for (int q = 0; q < NQ; ++q) {
#pragma unroll
        for (int off = 16; off > 0; off >>= 1)
            red[q] += __shfl_xor_sync(0xffffffffu, red[q], off);
    }
    if (L == 0) {
#pragma unroll
        for (int q = 0; q < NQ; ++q) redsc[w][q] = red[q];
    }
    __syncthreads();
    if (t < NQ)
        out[b * NQ + t] = redsc[0][t] + redsc[1][t];
}

extern "C" void kernel_launch(void* const* d_in, const int* in_sizes, int n_in,
                              void* d_out, int out_size) {
    const float* x = (const float*)d_in[0];
    const float* w = (const float*)d_in[1];
    if (n_in >= 2 && in_sizes[0] == NG * 3 && in_sizes[1] != NG * 3) {
        x = (const float*)d_in[1];
        w = (const float*)d_in[0];
    }
    // Keep the driver from shrinking the smem carveout below 12 blocks' worth.
    static bool attr_set = false;
    if (!attr_set) {
        cudaFuncSetAttribute(vq_main,
                             cudaFuncAttributePreferredSharedMemoryCarveout, 50);
        attr_set = true;
    }
    const int batch = out_size / NQ;            // 16384
    vq_prep<<<1, 32>>>(w);
    vq_main<<<batch, 64>>>(x, (float*)d_out);
}

// round 11
// speedup vs baseline: 1.2036x; 1.0806x over previous
#include <cuda_runtime.h>
#include <math.h>

#define NQ       10
#define DIM      1024
#define NL       3
#define NG       (NL * NQ)
#define PI_F     3.14159265358979f

// ---------------- packed f32x2 helpers (sm_103a) ----------------
union F2U { float2 f; unsigned long long u; };

__device__ __forceinline__ float2 f2mul(float2 a, float2 b) {
    F2U A, B, D; A.f = a; B.f = b;
    asm("mul.rn.f32x2 %0, %1, %2;" : "=l"(D.u) : "l"(A.u), "l"(B.u));
    return D.f;
}
__device__ __forceinline__ float2 f2fma(float2 a, float2 b, float2 c) {
    F2U A, B, C, D; A.f = a; B.f = b; C.f = c;
    asm("fma.rn.f32x2 %0, %1, %2, %3;" : "=l"(D.u) : "l"(A.u), "l"(B.u), "l"(C.u));
    return D.f;
}
__device__ __forceinline__ float2 cmul(float2 a, float2 b) {
    return make_float2(a.x * b.x - a.y * b.y, a.x * b.y + a.y * b.x);
}

// Composed 10-CNOT ring: state_new[k] = state_old[P(k)]
__device__ __forceinline__ int cnot_perm(int k) {
    return k ^ (k >> 1) ^ ((-(k & 1)) & 0x300);
}

// XOR bank swizzle: injects bits 8..5 into bits 3..0 (conflict-free for all
// access patterns below; verified bit-by-bit).
__device__ __forceinline__ int physk(int k) { return k ^ ((k >> 5) & 15); }

// Canonical index of thread-local amp r for each layout (L=lane, w=warp bit).
// Layout1: k = [L4..L0 | w | r3..r0]          (reg bits = qubits 6..9)
__device__ __forceinline__ int k1i(int L, int w, int r) {
    return (L << 5) | (w << 4) | r;
}
// Layout2: k = [L4 L3 | r3..r0 | w | L2 L1 L0] (reg bits = qubits 2..5)
__device__ __forceinline__ int k2i(int L, int w, int r) {
    return ((L & 24) << 5) | (r << 4) | (w << 3) | (L & 7);
}
// Layout3: k = [r3 r2 | L4 L3 L2 | w | L1 L0 | r1 r0] (reg bits incl. qubits 0,1)
__device__ __forceinline__ int k3i(int L, int w, int r) {
    return ((r & 12) << 6) | ((L & 28) << 3) | (w << 4) | ((L & 3) << 2) | (r & 3);
}

// Gate coefficients packed per u-element as (x, x, -y, y); order u00,u01,u10,u11.
__device__ float4 g_gco[NG][4];

// ---------------- prep: fuse RZ*RY*RX per (layer,qubit) ----------------
__global__ void vq_prep(const float* __restrict__ w) {
    const int t = threadIdx.x;
    if (t >= NG) return;
    const float ax = w[t * 3 + 0], ay = w[t * 3 + 1], az = w[t * 3 + 2];
    float ca, sa, cb, sb, cg, sg;
    sincosf(0.5f * ax, &sa, &ca);
    sincosf(0.5f * ay, &sb, &cb);
    sincosf(0.5f * az, &sg, &cg);
    const float2 M00 = make_float2( cb * ca,  sb * sa);
    const float2 M01 = make_float2(-sb * ca, -cb * sa);
    const float2 M10 = make_float2( sb * ca, -cb * sa);
    const float2 M11 = make_float2( cb * ca, -sb * sa);
    const float2 e0 = make_float2(cg, -sg);
    const float2 e1 = make_float2(cg,  sg);
    const float2 u00 = cmul(e0, M00), u01 = cmul(e0, M01);
    const float2 u10 = cmul(e1, M10), u11 = cmul(e1, M11);
    g_gco[t][0] = make_float4(u00.x, u00.x, -u00.y, u00.y);
    g_gco[t][1] = make_float4(u01.x, u01.x, -u01.y, u01.y);
    g_gco[t][2] = make_float4(u10.x, u10.x, -u10.y, u10.y);
    g_gco[t][3] = make_float4(u11.x, u11.x, -u11.y, u11.y);
}

// Apply fused gate with register-bit mask RM to 16 register-resident amps.
template<int RM>
__device__ __forceinline__ void apply_gate16(float2 a[16], int g) {
    const float4 q0 = __ldg(&g_gco[g][0]);
    const float4 q1 = __ldg(&g_gco[g][1]);
    const float4 q2 = __ldg(&g_gco[g][2]);
    const float4 q3 = __ldg(&g_gco[g][3]);
    const float2 u00x = make_float2(q0.x, q0.y), u00m = make_float2(q0.z, q0.w);
    const float2 u01x = make_float2(q1.x, q1.y), u01m = make_float2(q1.z, q1.w);
    const float2 u10x = make_float2(q2.x, q2.y), u10m = make_float2(q2.z, q2.w);
    const float2 u11x = make_float2(q3.x, q3.y), u11m = make_float2(q3.z, q3.w);
#pragma unroll
    for (int r = 0; r < 16; ++r) {
        if (r & RM) continue;
        const float2 a0 = a[r];
        const float2 a1 = a[r | RM];
        const float2 s0 = make_float2(a0.y, a0.x);
        const float2 s1 = make_float2(a1.y, a1.x);
        float2 r0 = f2mul(u00x, a0);
        r0 = f2fma(u00m, s0, r0);
        r0 = f2fma(u01x, a1, r0);
        r0 = f2fma(u01m, s1, r0);
        float2 r1 = f2mul(u10x, a0);
        r1 = f2fma(u10m, s0, r1);
        r1 = f2fma(u11x, a1, r1);
        r1 = f2fma(u11m, s1, r1);
        a[r]      = r0;
        a[r | RM] = r1;
    }
}

// ---------------- main: 1 block (2 warps, 64 thr) = 1 batch element ----------------
// minocc 10 -> 102-reg budget: enough for the true live set, NO spills.
__global__ __launch_bounds__(64, 10)
void vq_main(const float* __restrict__ x, float* __restrict__ out) {
    __shared__ float2 S[DIM];              // 8 KB statevector buffer
    __shared__ float  redsc[2][NQ];

    const int t = threadIdx.x;
    const int w = t >> 5;                  // warp bit (qubit position per layouts)
    const int L = t & 31;
    const int b = blockIdx.x;

    // ---- encoding angles (lanes 0..9 compute, shfl broadcast within warp) ----
    float c = 1.0f, s = 0.0f;
    if (L < NQ) {
        const float a = tanhf(x[b * NQ + L]) * PI_F;
        sincosf(0.5f * a, &s, &c);
    }
    float cq[NQ], sq[NQ];
#pragma unroll
    for (int q = 0; q < NQ; ++q) {
        cq[q] = __shfl_sync(0xffffffffu, c, q);
        sq[q] = __shfl_sync(0xffffffffu, s, q);
    }

    // ---- initial state = enc evaluated at P(k1)  (layer-0 perm folded in) ----
    float2 a[16];
#pragma unroll
    for (int r = 0; r < 16; ++r) {
        const int j = cnot_perm(k1i(L, w, r));
        float f = 1.0f;
#pragma unroll
        for (int q = 0; q < NQ; ++q)
            f *= ((j >> (9 - q)) & 1) ? sq[q] : cq[q];
        a[r] = make_float2(f, 0.0f);
    }

    // ---- layers ----
#pragma unroll
    for (int l = 0; l < NL; ++l) {
        if (l > 0) {
            // CNOT-ring permutation: layout3 -> gather P -> layout1
            __syncthreads();
#pragma unroll
            for (int r = 0; r < 16; ++r) S[physk(k3i(L, w, r))] = a[r];
            __syncthreads();
#pragma unroll
            for (int r = 0; r < 16; ++r) a[r] = S[physk(cnot_perm(k1i(L, w, r)))];
        }

        // phase 1 (layout1): qubits 6..9 on reg bits 3..0
        apply_gate16<8>(a, l * NQ + 6);
        apply_gate16<4>(a, l * NQ + 7);
        apply_gate16<2>(a, l * NQ + 8);
        apply_gate16<1>(a, l * NQ + 9);

        // relayout 1 -> 2
        __syncthreads();
#pragma unroll
        for (int r = 0; r < 16; ++r) S[physk(k1i(L, w, r))] = a[r];
        __syncthreads();
#pragma unroll
        for (int r = 0; r < 16; ++r) a[r] = S[physk(k2i(L, w, r))];

        // phase 2 (layout2): qubits 2..5 on reg bits 3..0
        apply_gate16<8>(a, l * NQ + 2);
        apply_gate16<4>(a, l * NQ + 3);
        apply_gate16<2>(a, l * NQ + 4);
        apply_gate16<1>(a, l * NQ + 5);

        // relayout 2 -> 3
        __syncthreads();
#pragma unroll
        for (int r = 0; r < 16; ++r) S[physk(k2i(L, w, r))] = a[r];
        __syncthreads();
#pragma unroll
        for (int r = 0; r < 16; ++r) a[r] = S[physk(k3i(L, w, r))];

        // phase 3 (layout3): qubits 0,1 on reg bits 3,2
        apply_gate16<8>(a, l * NQ + 0);
        apply_gate16<4>(a, l * NQ + 1);
    }

    // ---- Z expectations (layout3 bit map):
    // q0:r3  q1:r2  q2:L4  q3:L3  q4:L2  q5:w  q6:L1  q7:L0  q8:r1  q9:r0
    float T = 0.0f, A0 = 0.0f, A1 = 0.0f, A8 = 0.0f, A9 = 0.0f;
#pragma unroll
    for (int r = 0; r < 16; ++r) {
        const float p = a[r].x * a[r].x + a[r].y * a[r].y;
        T  += p;
        A0 += (r & 8) ? -p : p;
        A1 += (r & 4) ? -p : p;
        A8 += (r & 2) ? -p : p;
        A9 += (r & 1) ? -p : p;
    }
    float red[NQ];
    red[0] = A0;
    red[1] = A1;
    red[2] = (L & 16) ? -T : T;
    red[3] = (L & 8)  ? -T : T;
    red[4] = (L & 4)  ? -T : T;
    red[5] = w        ? -T : T;
    red[6] = (L & 2)  ? -T : T;
    red[7] = (L & 1)  ? -T : T;
    red[8] = A8;
    red[9] = A9;

#pragma unroll
    for (int q = 0; q < NQ; ++q) {
#pragma unroll
        for (int off = 16; off > 0; off >>= 1)
            red[q] += __shfl_xor_sync(0xffffffffu, red[q], off);
    }
    if (L == 0) {
#pragma unroll
        for (int q = 0; q < NQ; ++q) redsc[w][q] = red[q];
    }
    __syncthreads();
    if (t < NQ)
        out[b * NQ + t] = redsc[0][t] + redsc[1][t];
}

extern "C" void kernel_launch(void* const* d_in, const int* in_sizes, int n_in,
                              void* d_out, int out_size) {
    const float* x = (const float*)d_in[0];
    const float* w = (const float*)d_in[1];
    if (n_in >= 2 && in_sizes[0] == NG * 3 && in_sizes[1] != NG * 3) {
        x = (const float*)d_in[1];
        w = (const float*)d_in[0];
    }
    // Bias the L1/smem carveout so ~11 blocks' worth of smem stays available.
    static bool attr_set = false;
    if (!attr_set) {
        cudaFuncSetAttribute(vq_main,
                             cudaFuncAttributePreferredSharedMemoryCarveout, 50);
        attr_set = true;
    }
    const int batch = out_size / NQ;            // 16384
    vq_prep<<<1, 32>>>(w);
    vq_main<<<batch, 64>>>(x, (float*)d_out);
}